// round 12
// baseline (speedup 1.0000x reference)
#include <cuda_runtime.h>
#include <cuda_bf16.h>

#define NN 50000
#define NE 800000
#define NET (NE + NN)
#define HEADS 4
#define HID 64
#define D1 256            // HEADS*HID
#define IND 128
#define EMB 128
#define NG 64

typedef unsigned long long ull;

// ---------------- scratch ----------------
__device__ __align__(16) __nv_bfloat16 g_h1[(size_t)NN * D1];   // bf16 messages L1
__device__ __align__(16) float         g_act1[(size_t)NN * D1]; // fp32 (gemm2 input)
__device__ __align__(16) __nv_bfloat16 g_h2[(size_t)NN * EMB];  // bf16 messages L2
__device__ __align__(16) float g_as1[NN * HEADS];
__device__ __align__(16) float g_ad1[NN * HEADS];
__device__ __align__(16) float g_as2[NN];
__device__ __align__(16) float g_ad2[NN];
__device__ __align__(16) float g_pool[NG * EMB];
__device__ __align__(16) float g_cnt[NG];
__device__ __align__(16) int   g_src[NET];
__device__ __align__(16) int   g_dst[NET];
__device__ __align__(16) int   g_batch[NN];
__device__ __align__(16) int   g_rowptr[NN + 1];
__device__ __align__(16) int   g_wp[NN];
__device__ __align__(16) int   g_csrc[NET];

// ---------------- helpers ----------------
__device__ __forceinline__ float elu1(float x)  { return x > 0.f ? x : expm1f(x); }
__device__ __forceinline__ float lrelu(float x) { return x > 0.f ? x : 0.2f * x; }

__device__ __forceinline__ void red4(float* p, float a, float b, float c, float d) {
    asm volatile("red.global.add.v4.f32 [%0], {%1, %2, %3, %4};"
                 :: "l"(p), "f"(a), "f"(b), "f"(c), "f"(d) : "memory");
}
__device__ __forceinline__ void ffma2(ull& d, ull a, ull b) {
    asm("fma.rn.f32x2 %0, %1, %2, %0;" : "+l"(d) : "l"(a), "l"(b));
}
__device__ __forceinline__ ull pack2(float lo, float hi) {
    ull r; asm("mov.b64 %0, {%1, %2};" : "=l"(r) : "f"(lo), "f"(hi)); return r;
}
__device__ __forceinline__ void unpack2(float& lo, float& hi, ull v) {
    asm("mov.b64 {%0, %1}, %2;" : "=f"(lo), "=f"(hi) : "l"(v));
}
__device__ __forceinline__ unsigned bfpack(float lo, float hi) {
    unsigned r;
    asm("cvt.rn.bf16x2.f32 %0, %1, %2;" : "=r"(r) : "f"(hi), "f"(lo));
    return r;
}
__device__ __forceinline__ float bflo(unsigned u) { return __uint_as_float(u << 16); }
__device__ __forceinline__ float bfhi(unsigned u) { return __uint_as_float(u & 0xffff0000u); }

// ---------------- prep / CSR ----------------
__global__ __launch_bounds__(256) void prep_kernel(const void* ei_raw, const void* b_raw) {
    const int*       e32 = (const int*)ei_raw;
    const long long* e64 = (const long long*)ei_raw;
    bool is64 = true;
#pragma unroll
    for (int i = 0; i < 16; i++) is64 &= (e32[2 * i + 1] == 0);

    int idx = blockIdx.x * blockDim.x + threadIdx.x;
    if (idx < NET) {
        int s, d;
        if (idx < NE) {
            if (is64) { s = (int)e64[idx]; d = (int)e64[NE + idx]; }
            else      { s = e32[idx];      d = e32[NE + idx]; }
        } else { s = d = idx - NE; }
        g_src[idx] = s;
        g_dst[idx] = d;
    }
    if (idx < NN) {
        g_batch[idx] = is64 ? (int)((const long long*)b_raw)[idx] : ((const int*)b_raw)[idx];
        g_wp[idx] = 0;
    }
    if (idx < NG * EMB) g_pool[idx] = 0.f;
    if (idx < NG)       g_cnt[idx]  = 0.f;
}

__global__ __launch_bounds__(256) void deg_kernel() {
    int idx = blockIdx.x * blockDim.x + threadIdx.x;
    if (idx < NET) atomicAdd(&g_wp[g_dst[idx]], 1);
    if (idx < NN)  atomicAdd(&g_cnt[g_batch[idx]], 1.f);
}

__global__ __launch_bounds__(1024) void scan_kernel() {
    __shared__ int part[1024];
    int t = threadIdx.x;
    const int CH = (NN + 1023) / 1024;
    int beg = t * CH, end = min(beg + CH, NN);
    int sum = 0;
    for (int i = beg; i < end; i++) sum += g_wp[i];
    part[t] = sum;
    __syncthreads();
    for (int off = 1; off < 1024; off <<= 1) {
        int v = (t >= off) ? part[t - off] : 0;
        __syncthreads();
        part[t] += v;
        __syncthreads();
    }
    int run = (t == 0) ? 0 : part[t - 1];
    for (int i = beg; i < end; i++) {
        int c = g_wp[i];
        g_rowptr[i] = run;
        g_wp[i] = run;
        run += c;
    }
    if (t == 1023) g_rowptr[NN] = run;
}

__global__ __launch_bounds__(256) void fill_kernel() {
    int e = blockIdx.x * blockDim.x + threadIdx.x;
    if (e >= NET) return;
    int pos = atomicAdd(&g_wp[g_dst[e]], 1);
    g_csrc[pos] = g_src[e];
}

// ---------------- f32x2 GEMM + fused attention-dot epilogue ----------------
// (unchanged from R11 — this round captures its ncu profile)
__global__ __launch_bounds__(256, 2) void gemm_kernel(
    const float* __restrict__ A, const float* __restrict__ B, __nv_bfloat16* __restrict__ C,
    int M, int N, int K,
    const float* __restrict__ avec, const float* __restrict__ dvec,
    float* __restrict__ as_out, float* __restrict__ ad_out, int multihead)
{
    __shared__ float As[8][132];
    __shared__ float Bs[8][132];

    int tid = threadIdx.x;
    int lane = tid & 31;
    int rowBase = blockIdx.x * 128;
    int colBase = blockIdx.y * 128;
    int tx = tid & 15;
    int ty = tid >> 4;

    ull acc[4][8];
#pragma unroll
    for (int p = 0; p < 4; p++)
#pragma unroll
        for (int j = 0; j < 8; j++) acc[p][j] = 0ull;

    int arow = rowBase + (tid >> 1);
    int akoff = (tid & 1) * 4;
    int brow = tid >> 5;
    int bcol = colBase + (tid & 31) * 4;
    int r = tid >> 1;

    for (int k0 = 0; k0 < K; k0 += 8) {
        float4 av = make_float4(0.f, 0.f, 0.f, 0.f);
        if (arow < M) av = *(const float4*)(A + (long long)arow * K + k0 + akoff);
        float4 bv = *(const float4*)(B + (long long)(k0 + brow) * N + bcol);
        As[akoff + 0][r] = av.x; As[akoff + 1][r] = av.y;
        As[akoff + 2][r] = av.z; As[akoff + 3][r] = av.w;
        *(float4*)&Bs[brow][(tid & 31) * 4] = bv;
        __syncthreads();
#pragma unroll
        for (int kk = 0; kk < 8; kk++) {
            ulonglong2 a01 = *(const ulonglong2*)&As[kk][ty * 8];
            ulonglong2 a23 = *(const ulonglong2*)&As[kk][ty * 8 + 4];
            float4 b0 = *(const float4*)&Bs[kk][tx * 8];
            float4 b1 = *(const float4*)&Bs[kk][tx * 8 + 4];
            ull rb[8];
            rb[0] = pack2(b0.x, b0.x); rb[1] = pack2(b0.y, b0.y);
            rb[2] = pack2(b0.z, b0.z); rb[3] = pack2(b0.w, b0.w);
            rb[4] = pack2(b1.x, b1.x); rb[5] = pack2(b1.y, b1.y);
            rb[6] = pack2(b1.z, b1.z); rb[7] = pack2(b1.w, b1.w);
            ull ra[4] = {a01.x, a01.y, a23.x, a23.y};
#pragma unroll
            for (int p = 0; p < 4; p++)
#pragma unroll
                for (int j = 0; j < 8; j++) ffma2(acc[p][j], ra[p], rb[j]);
        }
        __syncthreads();
    }

    // ---- epilogue: bf16 C store + fused attention dots (fp32) ----
    float4 av0 = *(const float4*)(avec + colBase + tx * 8);
    float4 av1 = *(const float4*)(avec + colBase + tx * 8 + 4);
    float4 dv0 = *(const float4*)(dvec + colBase + tx * 8);
    float4 dv1 = *(const float4*)(dvec + colBase + tx * 8 + 4);
    float ds[8], dd[8];

#pragma unroll
    for (int p = 0; p < 4; p++) {
        float lo[8], hi[8];
#pragma unroll
        for (int j = 0; j < 8; j++) unpack2(lo[j], hi[j], acc[p][j]);
        int m0 = rowBase + ty * 8 + 2 * p;
        long long cbase = (long long)m0 * N + colBase + tx * 8;
        if (m0 < M) {
            uint4 u;
            u.x = bfpack(lo[0], lo[1]); u.y = bfpack(lo[2], lo[3]);
            u.z = bfpack(lo[4], lo[5]); u.w = bfpack(lo[6], lo[7]);
            *(uint4*)(C + cbase) = u;
        }
        if (m0 + 1 < M) {
            uint4 u;
            u.x = bfpack(hi[0], hi[1]); u.y = bfpack(hi[2], hi[3]);
            u.z = bfpack(hi[4], hi[5]); u.w = bfpack(hi[6], hi[7]);
            *(uint4*)(C + cbase + N) = u;
        }
        ds[2*p]   = lo[0]*av0.x + lo[1]*av0.y + lo[2]*av0.z + lo[3]*av0.w
                  + lo[4]*av1.x + lo[5]*av1.y + lo[6]*av1.z + lo[7]*av1.w;
        dd[2*p]   = lo[0]*dv0.x + lo[1]*dv0.y + lo[2]*dv0.z + lo[3]*dv0.w
                  + lo[4]*dv1.x + lo[5]*dv1.y + lo[6]*dv1.z + lo[7]*dv1.w;
        ds[2*p+1] = hi[0]*av0.x + hi[1]*av0.y + hi[2]*av0.z + hi[3]*av0.w
                  + hi[4]*av1.x + hi[5]*av1.y + hi[6]*av1.z + hi[7]*av1.w;
        dd[2*p+1] = hi[0]*dv0.x + hi[1]*dv0.y + hi[2]*dv0.z + hi[3]*dv0.w
                  + hi[4]*dv1.x + hi[5]*dv1.y + hi[6]*dv1.z + hi[7]*dv1.w;
    }
#pragma unroll
    for (int rr = 0; rr < 8; rr++) {
        ds[rr] += __shfl_xor_sync(0xffffffffu, ds[rr], 1);
        ds[rr] += __shfl_xor_sync(0xffffffffu, ds[rr], 2);
        ds[rr] += __shfl_xor_sync(0xffffffffu, ds[rr], 4);
        dd[rr] += __shfl_xor_sync(0xffffffffu, dd[rr], 1);
        dd[rr] += __shfl_xor_sync(0xffffffffu, dd[rr], 2);
        dd[rr] += __shfl_xor_sync(0xffffffffu, dd[rr], 4);
        if (!multihead) {
            ds[rr] += __shfl_xor_sync(0xffffffffu, ds[rr], 8);
            dd[rr] += __shfl_xor_sync(0xffffffffu, dd[rr], 8);
        }
    }
    int rowb = rowBase + ty * 8;
    if (multihead) {
        if ((lane & 7) == 0) {
            int head = (colBase >> 6) + ((lane >> 3) & 1);
#pragma unroll
            for (int rr = 0; rr < 8; rr++) {
                int row = rowb + rr;
                if (row < M) {
                    as_out[row * 4 + head] = ds[rr];
                    ad_out[row * 4 + head] = dd[rr];
                }
            }
        }
    } else {
        if ((lane & 15) == 0) {
#pragma unroll
            for (int rr = 0; rr < 8; rr++) {
                int row = rowb + rr;
                if (row < M) {
                    as_out[row] = ds[rr];
                    ad_out[row] = dd[rr];
                }
            }
        }
    }
}

// ---------------- CSR aggregation (warp per dst node, 2-edge unrolled) ----------------
__global__ __launch_bounds__(256) void agg1_kernel(const float* __restrict__ b1) {
    int d = (blockIdx.x * blockDim.x + threadIdx.x) >> 5;
    int lane = threadIdx.x & 31;
    if (d >= NN) return;
    int h = lane >> 3;
    float ad = g_ad1[d * 4 + h];
    int beg = g_rowptr[d], end = g_rowptr[d + 1];
    float z = 0.f;
    float a[8] = {0.f, 0.f, 0.f, 0.f, 0.f, 0.f, 0.f, 0.f};
    int i = beg;
    for (; i + 2 <= end; i += 2) {
        int s0 = g_csrc[i], s1 = g_csrc[i + 1];
        float e0 = g_as1[s0 * 4 + h], e1 = g_as1[s1 * 4 + h];
        uint4 v0 = *(const uint4*)(g_h1 + (size_t)s0 * D1 + lane * 8);
        uint4 v1 = *(const uint4*)(g_h1 + (size_t)s1 * D1 + lane * 8);
        float w0 = __expf(lrelu(e0 + ad));
        float w1 = __expf(lrelu(e1 + ad));
        z += w0 + w1;
        a[0] += w0 * bflo(v0.x) + w1 * bflo(v1.x);
        a[1] += w0 * bfhi(v0.x) + w1 * bfhi(v1.x);
        a[2] += w0 * bflo(v0.y) + w1 * bflo(v1.y);
        a[3] += w0 * bfhi(v0.y) + w1 * bfhi(v1.y);
        a[4] += w0 * bflo(v0.z) + w1 * bflo(v1.z);
        a[5] += w0 * bfhi(v0.z) + w1 * bfhi(v1.z);
        a[6] += w0 * bflo(v0.w) + w1 * bflo(v1.w);
        a[7] += w0 * bfhi(v0.w) + w1 * bfhi(v1.w);
    }
    if (i < end) {
        int s = g_csrc[i];
        float w = __expf(lrelu(g_as1[s * 4 + h] + ad));
        uint4 v = *(const uint4*)(g_h1 + (size_t)s * D1 + lane * 8);
        z += w;
        a[0] += w * bflo(v.x); a[1] += w * bfhi(v.x);
        a[2] += w * bflo(v.y); a[3] += w * bfhi(v.y);
        a[4] += w * bflo(v.z); a[5] += w * bfhi(v.z);
        a[6] += w * bflo(v.w); a[7] += w * bfhi(v.w);
    }
    float inv = 1.f / z;
    const float4* bb = (const float4*)(b1 + lane * 8);
    float4 c0 = bb[0], c1 = bb[1];
    float4 o0, o1;
    o0.x = elu1(a[0] * inv + c0.x); o0.y = elu1(a[1] * inv + c0.y);
    o0.z = elu1(a[2] * inv + c0.z); o0.w = elu1(a[3] * inv + c0.w);
    o1.x = elu1(a[4] * inv + c1.x); o1.y = elu1(a[5] * inv + c1.y);
    o1.z = elu1(a[6] * inv + c1.z); o1.w = elu1(a[7] * inv + c1.w);
    float4* op = (float4*)(g_act1 + (size_t)d * D1 + lane * 8);
    op[0] = o0; op[1] = o1;
}

__global__ __launch_bounds__(256) void agg2_kernel(const float* __restrict__ b2) {
    int d = (blockIdx.x * blockDim.x + threadIdx.x) >> 5;
    int lane = threadIdx.x & 31;
    if (d >= NN) return;
    float ad = g_ad2[d];
    int beg = g_rowptr[d], end = g_rowptr[d + 1];
    float z = 0.f;
    float a[4] = {0.f, 0.f, 0.f, 0.f};
    int i = beg;
    for (; i + 2 <= end; i += 2) {
        int s0 = g_csrc[i], s1 = g_csrc[i + 1];
        float e0 = g_as2[s0], e1 = g_as2[s1];
        uint2 v0 = *(const uint2*)(g_h2 + (size_t)s0 * EMB + lane * 4);
        uint2 v1 = *(const uint2*)(g_h2 + (size_t)s1 * EMB + lane * 4);
        float w0 = __expf(lrelu(e0 + ad));
        float w1 = __expf(lrelu(e1 + ad));
        z += w0 + w1;
        a[0] += w0 * bflo(v0.x) + w1 * bflo(v1.x);
        a[1] += w0 * bfhi(v0.x) + w1 * bfhi(v1.x);
        a[2] += w0 * bflo(v0.y) + w1 * bflo(v1.y);
        a[3] += w0 * bfhi(v0.y) + w1 * bfhi(v1.y);
    }
    if (i < end) {
        int s = g_csrc[i];
        float w = __expf(lrelu(g_as2[s] + ad));
        uint2 v = *(const uint2*)(g_h2 + (size_t)s * EMB + lane * 4);
        z += w;
        a[0] += w * bflo(v.x); a[1] += w * bfhi(v.x);
        a[2] += w * bflo(v.y); a[3] += w * bfhi(v.y);
    }
    float inv = 1.f / z;
    float4 c = ((const float4*)b2)[lane];
    float o0 = elu1(a[0] * inv + c.x), o1 = elu1(a[1] * inv + c.y);
    float o2 = elu1(a[2] * inv + c.z), o3 = elu1(a[3] * inv + c.w);
    int b = g_batch[d];
    red4(&g_pool[b * EMB + lane * 4], o0, o1, o2, o3);
}

__global__ __launch_bounds__(256) void final_div_kernel(float* __restrict__ out) {
    int i = blockIdx.x * blockDim.x + threadIdx.x;
    if (i >= NG * EMB) return;
    out[i] = g_pool[i] / fmaxf(g_cnt[i >> 7], 1.f);
}

// ---------------- launcher ----------------
extern "C" void kernel_launch(void* const* d_in, const int* in_sizes, int n_in,
                              void* d_out, int out_size)
{
    const float* x      = (const float*)d_in[0];
    const void*  ei     = d_in[1];
    const void*  batch  = d_in[3];
    const float* W1     = (const float*)d_in[4];
    const float* a_src1 = (const float*)d_in[5];
    const float* a_dst1 = (const float*)d_in[6];
    const float* b1     = (const float*)d_in[7];
    const float* W2     = (const float*)d_in[8];
    const float* a_src2 = (const float*)d_in[9];
    const float* a_dst2 = (const float*)d_in[10];
    const float* b2     = (const float*)d_in[11];
    float*       out    = (float*)d_out;

    __nv_bfloat16 *p_h1, *p_h2;
    float *p_act1, *p_as1, *p_ad1, *p_as2, *p_ad2;
    cudaGetSymbolAddress((void**)&p_h1,   g_h1);
    cudaGetSymbolAddress((void**)&p_act1, g_act1);
    cudaGetSymbolAddress((void**)&p_h2,   g_h2);
    cudaGetSymbolAddress((void**)&p_as1,  g_as1);
    cudaGetSymbolAddress((void**)&p_ad1,  g_ad1);
    cudaGetSymbolAddress((void**)&p_as2,  g_as2);
    cudaGetSymbolAddress((void**)&p_ad2,  g_ad2);

    static cudaStream_t s_side = nullptr;
    static cudaEvent_t  ev_fork = nullptr, ev_join = nullptr;
    if (!s_side) {
        cudaStreamCreateWithFlags(&s_side, cudaStreamNonBlocking);
        cudaEventCreateWithFlags(&ev_fork, cudaEventDisableTiming);
        cudaEventCreateWithFlags(&ev_join, cudaEventDisableTiming);
    }

    // fork: CSR build concurrent with GEMM1.
    // Submission order puts gemm1 4th so ncu (-s bounded) profiles it.
    cudaEventRecord(ev_fork, 0);
    cudaStreamWaitEvent(s_side, ev_fork, 0);
    prep_kernel<<<(NET + 255) / 256, 256, 0, s_side>>>(ei, batch);   // 1
    deg_kernel<<<(NET + 255) / 256, 256, 0, s_side>>>();             // 2
    scan_kernel<<<1, 1024, 0, s_side>>>();                           // 3

    gemm_kernel<<<dim3((NN + 127) / 128, D1 / 128), 256>>>(          // 4  <- profiled
        x, W1, p_h1, NN, D1, IND, a_src1, a_dst1, p_as1, p_ad1, 1);

    fill_kernel<<<(NET + 255) / 256, 256, 0, s_side>>>();            // 5
    cudaEventRecord(ev_join, s_side);

    cudaStreamWaitEvent(0, ev_join, 0);
    agg1_kernel<<<(NN + 7) / 8, 256>>>(b1);                          // 6

    gemm_kernel<<<dim3((NN + 127) / 128, EMB / 128), 256>>>(         // 7
        p_act1, W2, p_h2, NN, EMB, D1, a_src2, a_dst2, p_as2, p_ad2, 0);
    agg2_kernel<<<(NN + 7) / 8, 256>>>(b2);                          // 8
    final_div_kernel<<<(NG * EMB + 255) / 256, 256>>>(out);          // 9
}

// round 13
// speedup vs baseline: 1.0300x; 1.0300x over previous
#include <cuda_runtime.h>
#include <cuda_bf16.h>

#define NN 50000
#define NE 800000
#define NET (NE + NN)
#define HEADS 4
#define HID 64
#define D1 256            // HEADS*HID
#define IND 128
#define EMB 128
#define NG 64

typedef unsigned long long ull;

// ---------------- scratch ----------------
__device__ __align__(16) __nv_bfloat16 g_h1[(size_t)NN * D1];   // bf16 messages L1
__device__ __align__(16) float         g_act1[(size_t)NN * D1]; // fp32 (gemm2 input)
__device__ __align__(16) __nv_bfloat16 g_h2[(size_t)NN * EMB];  // bf16 messages L2
__device__ __align__(16) float g_as1[NN * HEADS];
__device__ __align__(16) float g_ad1[NN * HEADS];
__device__ __align__(16) float g_as2[NN];
__device__ __align__(16) float g_ad2[NN];
__device__ __align__(16) float g_pool[NG * EMB];
__device__ __align__(16) float g_cnt[NG];
__device__ __align__(16) int   g_src[NET];
__device__ __align__(16) int   g_dst[NET];
__device__ __align__(16) int   g_batch[NN];
__device__ __align__(16) int   g_rowptr[NN + 1];
__device__ __align__(16) int   g_wp[NN];
__device__ __align__(16) int   g_csrc[NET];

// ---------------- helpers ----------------
__device__ __forceinline__ float elu1(float x)  { return x > 0.f ? x : expm1f(x); }
__device__ __forceinline__ float lrelu(float x) { return x > 0.f ? x : 0.2f * x; }

__device__ __forceinline__ void red4(float* p, float a, float b, float c, float d) {
    asm volatile("red.global.add.v4.f32 [%0], {%1, %2, %3, %4};"
                 :: "l"(p), "f"(a), "f"(b), "f"(c), "f"(d) : "memory");
}
__device__ __forceinline__ void ffma2(ull& d, ull a, ull b) {
    asm("fma.rn.f32x2 %0, %1, %2, %0;" : "+l"(d) : "l"(a), "l"(b));
}
__device__ __forceinline__ ull pack2(float lo, float hi) {
    ull r; asm("mov.b64 %0, {%1, %2};" : "=l"(r) : "f"(lo), "f"(hi)); return r;
}
__device__ __forceinline__ void unpack2(float& lo, float& hi, ull v) {
    asm("mov.b64 {%0, %1}, %2;" : "=f"(lo), "=f"(hi) : "l"(v));
}
__device__ __forceinline__ unsigned bfpack(float lo, float hi) {
    unsigned r;
    asm("cvt.rn.bf16x2.f32 %0, %1, %2;" : "=r"(r) : "f"(hi), "f"(lo));
    return r;
}
__device__ __forceinline__ float bflo(unsigned u) { return __uint_as_float(u << 16); }
__device__ __forceinline__ float bfhi(unsigned u) { return __uint_as_float(u & 0xffff0000u); }

// ---------------- prep / CSR ----------------
__global__ __launch_bounds__(256) void prep_kernel(const void* ei_raw, const void* b_raw) {
    const int*       e32 = (const int*)ei_raw;
    const long long* e64 = (const long long*)ei_raw;
    bool is64 = true;
#pragma unroll
    for (int i = 0; i < 16; i++) is64 &= (e32[2 * i + 1] == 0);

    int idx = blockIdx.x * blockDim.x + threadIdx.x;
    if (idx < NET) {
        int s, d;
        if (idx < NE) {
            if (is64) { s = (int)e64[idx]; d = (int)e64[NE + idx]; }
            else      { s = e32[idx];      d = e32[NE + idx]; }
        } else { s = d = idx - NE; }
        g_src[idx] = s;
        g_dst[idx] = d;
    }
    if (idx < NN) {
        g_batch[idx] = is64 ? (int)((const long long*)b_raw)[idx] : ((const int*)b_raw)[idx];
        g_wp[idx] = 0;
    }
    if (idx < NG * EMB) g_pool[idx] = 0.f;
    if (idx < NG)       g_cnt[idx]  = 0.f;
}

__global__ __launch_bounds__(256) void deg_kernel() {
    int idx = blockIdx.x * blockDim.x + threadIdx.x;
    if (idx < NET) atomicAdd(&g_wp[g_dst[idx]], 1);
    if (idx < NN)  atomicAdd(&g_cnt[g_batch[idx]], 1.f);
}

__global__ __launch_bounds__(1024) void scan_kernel() {
    __shared__ int part[1024];
    int t = threadIdx.x;
    const int CH = (NN + 1023) / 1024;
    int beg = t * CH, end = min(beg + CH, NN);
    int sum = 0;
    for (int i = beg; i < end; i++) sum += g_wp[i];
    part[t] = sum;
    __syncthreads();
    for (int off = 1; off < 1024; off <<= 1) {
        int v = (t >= off) ? part[t - off] : 0;
        __syncthreads();
        part[t] += v;
        __syncthreads();
    }
    int run = (t == 0) ? 0 : part[t - 1];
    for (int i = beg; i < end; i++) {
        int c = g_wp[i];
        g_rowptr[i] = run;
        g_wp[i] = run;
        run += c;
    }
    if (t == 1023) g_rowptr[NN] = run;
}

__global__ __launch_bounds__(256) void fill_kernel() {
    int e = blockIdx.x * blockDim.x + threadIdx.x;
    if (e >= NET) return;
    int pos = atomicAdd(&g_wp[g_dst[e]], 1);
    g_csrc[pos] = g_src[e];
}

// ---------------- f32x2 GEMM + fused attention-dot epilogue ----------------
// C[M,N] = A[M,K] @ B[K,N], stored bf16. BM=128, BN=128, BK=8, 256 threads,
// 8x8/thread (M-paired f32x2 accum). Thread cols split {tx*4, 64+tx*4}:
// B LDS reads are 16B-stride contiguous (2 wavefronts, was 4-way conflicted).
__global__ __launch_bounds__(256, 2) void gemm_kernel(
    const float* __restrict__ A, const float* __restrict__ B, __nv_bfloat16* __restrict__ C,
    int M, int N, int K,
    const float* __restrict__ avec, const float* __restrict__ dvec,
    float* __restrict__ as_out, float* __restrict__ ad_out, int multihead)
{
    __shared__ float As[8][132];
    __shared__ float Bs[8][132];

    int tid = threadIdx.x;
    int lane = tid & 31;
    int rowBase = blockIdx.x * 128;
    int colBase = blockIdx.y * 128;
    int tx = tid & 15;
    int ty = tid >> 4;

    ull acc[4][8];   // [row-pair p][col j]: j 0-3 -> cols tx*4+j, j 4-7 -> 64+tx*4+(j-4)
#pragma unroll
    for (int p = 0; p < 4; p++)
#pragma unroll
        for (int j = 0; j < 8; j++) acc[p][j] = 0ull;

    int arow = rowBase + (tid >> 1);
    int akoff = (tid & 1) * 4;
    int brow = tid >> 5;
    int bcol = colBase + (tid & 31) * 4;
    int r = tid >> 1;

    for (int k0 = 0; k0 < K; k0 += 8) {
        float4 av = make_float4(0.f, 0.f, 0.f, 0.f);
        if (arow < M) av = *(const float4*)(A + (long long)arow * K + k0 + akoff);
        float4 bv = *(const float4*)(B + (long long)(k0 + brow) * N + bcol);
        As[akoff + 0][r] = av.x; As[akoff + 1][r] = av.y;
        As[akoff + 2][r] = av.z; As[akoff + 3][r] = av.w;
        *(float4*)&Bs[brow][(tid & 31) * 4] = bv;
        __syncthreads();
#pragma unroll
        for (int kk = 0; kk < 8; kk++) {
            ulonglong2 a01 = *(const ulonglong2*)&As[kk][ty * 8];
            ulonglong2 a23 = *(const ulonglong2*)&As[kk][ty * 8 + 4];
            float4 b0 = *(const float4*)&Bs[kk][tx * 4];        // contiguous 256B span
            float4 b1 = *(const float4*)&Bs[kk][64 + tx * 4];
            ull rb[8];
            rb[0] = pack2(b0.x, b0.x); rb[1] = pack2(b0.y, b0.y);
            rb[2] = pack2(b0.z, b0.z); rb[3] = pack2(b0.w, b0.w);
            rb[4] = pack2(b1.x, b1.x); rb[5] = pack2(b1.y, b1.y);
            rb[6] = pack2(b1.z, b1.z); rb[7] = pack2(b1.w, b1.w);
            ull ra[4] = {a01.x, a01.y, a23.x, a23.y};
#pragma unroll
            for (int p = 0; p < 4; p++)
#pragma unroll
                for (int j = 0; j < 8; j++) ffma2(acc[p][j], ra[p], rb[j]);
        }
        __syncthreads();
    }

    // ---- epilogue: bf16 C store + fused attention dots (two col groups) ----
    float4 av0 = *(const float4*)(avec + colBase + tx * 4);
    float4 av1 = *(const float4*)(avec + colBase + 64 + tx * 4);
    float4 dv0 = *(const float4*)(dvec + colBase + tx * 4);
    float4 dv1 = *(const float4*)(dvec + colBase + 64 + tx * 4);
    float ds0[8], ds1[8], dd0[8], dd1[8];

#pragma unroll
    for (int p = 0; p < 4; p++) {
        float lo[8], hi[8];
#pragma unroll
        for (int j = 0; j < 8; j++) unpack2(lo[j], hi[j], acc[p][j]);
        int m0 = rowBase + ty * 8 + 2 * p;
        long long cb = (long long)m0 * N + colBase + tx * 4;
        if (m0 < M) {
            uint2 u0 = make_uint2(bfpack(lo[0], lo[1]), bfpack(lo[2], lo[3]));
            uint2 u1 = make_uint2(bfpack(lo[4], lo[5]), bfpack(lo[6], lo[7]));
            *(uint2*)(C + cb)      = u0;
            *(uint2*)(C + cb + 64) = u1;
        }
        if (m0 + 1 < M) {
            uint2 u0 = make_uint2(bfpack(hi[0], hi[1]), bfpack(hi[2], hi[3]));
            uint2 u1 = make_uint2(bfpack(hi[4], hi[5]), bfpack(hi[6], hi[7]));
            *(uint2*)(C + cb + N)      = u0;
            *(uint2*)(C + cb + N + 64) = u1;
        }
        ds0[2*p]   = lo[0]*av0.x + lo[1]*av0.y + lo[2]*av0.z + lo[3]*av0.w;
        ds1[2*p]   = lo[4]*av1.x + lo[5]*av1.y + lo[6]*av1.z + lo[7]*av1.w;
        dd0[2*p]   = lo[0]*dv0.x + lo[1]*dv0.y + lo[2]*dv0.z + lo[3]*dv0.w;
        dd1[2*p]   = lo[4]*dv1.x + lo[5]*dv1.y + lo[6]*dv1.z + lo[7]*dv1.w;
        ds0[2*p+1] = hi[0]*av0.x + hi[1]*av0.y + hi[2]*av0.z + hi[3]*av0.w;
        ds1[2*p+1] = hi[4]*av1.x + hi[5]*av1.y + hi[6]*av1.z + hi[7]*av1.w;
        dd0[2*p+1] = hi[0]*dv0.x + hi[1]*dv0.y + hi[2]*dv0.z + hi[3]*dv0.w;
        dd1[2*p+1] = hi[4]*dv1.x + hi[5]*dv1.y + hi[6]*dv1.z + hi[7]*dv1.w;
    }
    if (!multihead) {
#pragma unroll
        for (int rr = 0; rr < 8; rr++) { ds0[rr] += ds1[rr]; dd0[rr] += dd1[rr]; }
    }
#pragma unroll
    for (int rr = 0; rr < 8; rr++) {
#pragma unroll
        for (int off = 1; off <= 8; off <<= 1) {
            ds0[rr] += __shfl_xor_sync(0xffffffffu, ds0[rr], off);
            dd0[rr] += __shfl_xor_sync(0xffffffffu, dd0[rr], off);
        }
        if (multihead) {
#pragma unroll
            for (int off = 1; off <= 8; off <<= 1) {
                ds1[rr] += __shfl_xor_sync(0xffffffffu, ds1[rr], off);
                dd1[rr] += __shfl_xor_sync(0xffffffffu, dd1[rr], off);
            }
        }
    }
    int rowb = rowBase + ty * 8;
    if ((lane & 15) == 0) {
        if (multihead) {
            int h0 = colBase >> 6;   // this block covers heads h0 and h0+1
#pragma unroll
            for (int rr = 0; rr < 8; rr++) {
                int row = rowb + rr;
                if (row < M) {
                    as_out[row * 4 + h0]     = ds0[rr];
                    as_out[row * 4 + h0 + 1] = ds1[rr];
                    ad_out[row * 4 + h0]     = dd0[rr];
                    ad_out[row * 4 + h0 + 1] = dd1[rr];
                }
            }
        } else {
#pragma unroll
            for (int rr = 0; rr < 8; rr++) {
                int row = rowb + rr;
                if (row < M) {
                    as_out[row] = ds0[rr];
                    ad_out[row] = dd0[rr];
                }
            }
        }
    }
}

// ---------------- CSR aggregation (warp per dst node, R11 proven form) ----------------
__global__ __launch_bounds__(256) void agg1_kernel(const float* __restrict__ b1) {
    int d = (blockIdx.x * blockDim.x + threadIdx.x) >> 5;
    int lane = threadIdx.x & 31;
    if (d >= NN) return;
    int h = lane >> 3;
    float ad = g_ad1[d * 4 + h];
    int beg = g_rowptr[d], end = g_rowptr[d + 1];
    float z = 0.f;
    float a[8] = {0.f, 0.f, 0.f, 0.f, 0.f, 0.f, 0.f, 0.f};
    for (int i = beg; i < end; i++) {
        int s = g_csrc[i];
        float w = __expf(lrelu(g_as1[s * 4 + h] + ad));
        z += w;
        uint4 v = *(const uint4*)(g_h1 + (size_t)s * D1 + lane * 8);
        a[0] += w * bflo(v.x); a[1] += w * bfhi(v.x);
        a[2] += w * bflo(v.y); a[3] += w * bfhi(v.y);
        a[4] += w * bflo(v.z); a[5] += w * bfhi(v.z);
        a[6] += w * bflo(v.w); a[7] += w * bfhi(v.w);
    }
    float inv = 1.f / z;
    const float4* bb = (const float4*)(b1 + lane * 8);
    float4 c0 = bb[0], c1 = bb[1];
    float4 o0, o1;
    o0.x = elu1(a[0] * inv + c0.x); o0.y = elu1(a[1] * inv + c0.y);
    o0.z = elu1(a[2] * inv + c0.z); o0.w = elu1(a[3] * inv + c0.w);
    o1.x = elu1(a[4] * inv + c1.x); o1.y = elu1(a[5] * inv + c1.y);
    o1.z = elu1(a[6] * inv + c1.z); o1.w = elu1(a[7] * inv + c1.w);
    float4* op = (float4*)(g_act1 + (size_t)d * D1 + lane * 8);
    op[0] = o0; op[1] = o1;
}

__global__ __launch_bounds__(256) void agg2_kernel(const float* __restrict__ b2) {
    int d = (blockIdx.x * blockDim.x + threadIdx.x) >> 5;
    int lane = threadIdx.x & 31;
    if (d >= NN) return;
    float ad = g_ad2[d];
    int beg = g_rowptr[d], end = g_rowptr[d + 1];
    float z = 0.f;
    float a[4] = {0.f, 0.f, 0.f, 0.f};
    for (int i = beg; i < end; i++) {
        int s = g_csrc[i];
        float w = __expf(lrelu(g_as2[s] + ad));
        z += w;
        uint2 v = *(const uint2*)(g_h2 + (size_t)s * EMB + lane * 4);
        a[0] += w * bflo(v.x); a[1] += w * bfhi(v.x);
        a[2] += w * bflo(v.y); a[3] += w * bfhi(v.y);
    }
    float inv = 1.f / z;
    float4 c = ((const float4*)b2)[lane];
    float o0 = elu1(a[0] * inv + c.x), o1 = elu1(a[1] * inv + c.y);
    float o2 = elu1(a[2] * inv + c.z), o3 = elu1(a[3] * inv + c.w);
    int b = g_batch[d];
    red4(&g_pool[b * EMB + lane * 4], o0, o1, o2, o3);
}

__global__ __launch_bounds__(256) void final_div_kernel(float* __restrict__ out) {
    int i = blockIdx.x * blockDim.x + threadIdx.x;
    if (i >= NG * EMB) return;
    out[i] = g_pool[i] / fmaxf(g_cnt[i >> 7], 1.f);
}

// ---------------- launcher ----------------
extern "C" void kernel_launch(void* const* d_in, const int* in_sizes, int n_in,
                              void* d_out, int out_size)
{
    const float* x      = (const float*)d_in[0];
    const void*  ei     = d_in[1];
    const void*  batch  = d_in[3];
    const float* W1     = (const float*)d_in[4];
    const float* a_src1 = (const float*)d_in[5];
    const float* a_dst1 = (const float*)d_in[6];
    const float* b1     = (const float*)d_in[7];
    const float* W2     = (const float*)d_in[8];
    const float* a_src2 = (const float*)d_in[9];
    const float* a_dst2 = (const float*)d_in[10];
    const float* b2     = (const float*)d_in[11];
    float*       out    = (float*)d_out;

    __nv_bfloat16 *p_h1, *p_h2;
    float *p_act1, *p_as1, *p_ad1, *p_as2, *p_ad2;
    cudaGetSymbolAddress((void**)&p_h1,   g_h1);
    cudaGetSymbolAddress((void**)&p_act1, g_act1);
    cudaGetSymbolAddress((void**)&p_h2,   g_h2);
    cudaGetSymbolAddress((void**)&p_as1,  g_as1);
    cudaGetSymbolAddress((void**)&p_ad1,  g_ad1);
    cudaGetSymbolAddress((void**)&p_as2,  g_as2);
    cudaGetSymbolAddress((void**)&p_ad2,  g_ad2);

    static cudaStream_t s_side = nullptr;
    static cudaEvent_t  ev_fork = nullptr, ev_join = nullptr;
    if (!s_side) {
        cudaStreamCreateWithFlags(&s_side, cudaStreamNonBlocking);
        cudaEventCreateWithFlags(&ev_fork, cudaEventDisableTiming);
        cudaEventCreateWithFlags(&ev_join, cudaEventDisableTiming);
    }

    // fork: CSR build concurrent with GEMM1; gemm1 stays 4th-submitted
    // so ncu profiles it (verify the LDS-conflict fix).
    cudaEventRecord(ev_fork, 0);
    cudaStreamWaitEvent(s_side, ev_fork, 0);
    prep_kernel<<<(NET + 255) / 256, 256, 0, s_side>>>(ei, batch);   // 1
    deg_kernel<<<(NET + 255) / 256, 256, 0, s_side>>>();             // 2
    scan_kernel<<<1, 1024, 0, s_side>>>();                           // 3

    gemm_kernel<<<dim3((NN + 127) / 128, D1 / 128), 256>>>(          // 4  <- profiled
        x, W1, p_h1, NN, D1, IND, a_src1, a_dst1, p_as1, p_ad1, 1);

    fill_kernel<<<(NET + 255) / 256, 256, 0, s_side>>>();            // 5
    cudaEventRecord(ev_join, s_side);

    cudaStreamWaitEvent(0, ev_join, 0);
    agg1_kernel<<<(NN + 7) / 8, 256>>>(b1);                          // 6

    gemm_kernel<<<dim3((NN + 127) / 128, EMB / 128), 256>>>(         // 7
        p_act1, W2, p_h2, NN, EMB, D1, a_src2, a_dst2, p_as2, p_ad2, 0);
    agg2_kernel<<<(NN + 7) / 8, 256>>>(b2);                          // 8
    final_div_kernel<<<(NG * EMB + 255) / 256, 256>>>(out);          // 9
}

// round 14
// speedup vs baseline: 1.0690x; 1.0379x over previous
#include <cuda_runtime.h>
#include <cuda_bf16.h>

#define NN 50000
#define NE 800000
#define NET (NE + NN)
#define HEADS 4
#define HID 64
#define D1 256            // HEADS*HID
#define IND 128
#define EMB 128
#define NG 64

typedef unsigned long long ull;

// ---------------- scratch ----------------
__device__ __align__(16) __nv_bfloat16 g_h1[(size_t)NN * D1];   // bf16 messages L1
__device__ __align__(16) float         g_act1[(size_t)NN * D1]; // fp32 (gemm2 input)
__device__ __align__(16) __nv_bfloat16 g_h2[(size_t)NN * EMB];  // bf16 messages L2
__device__ __align__(16) float g_as1[NN * HEADS];
__device__ __align__(16) float g_ad1[NN * HEADS];
__device__ __align__(16) float g_as2[NN];
__device__ __align__(16) float g_ad2[NN];
__device__ __align__(16) float g_pool[NG * EMB];
__device__ __align__(16) float g_cnt[NG];
__device__ __align__(16) int   g_src[NET];
__device__ __align__(16) int   g_dst[NET];
__device__ __align__(16) int   g_batch[NN];
__device__ __align__(16) int   g_rowptr[NN + 1];
__device__ __align__(16) int   g_wp[NN];     // zeroed by cleanup_kernel each run
__device__ __align__(16) int   g_csrc[NET];

// ---------------- helpers ----------------
__device__ __forceinline__ float elu1(float x)  { return x > 0.f ? x : expm1f(x); }
__device__ __forceinline__ float lrelu(float x) { return x > 0.f ? x : 0.2f * x; }

__device__ __forceinline__ void red4(float* p, float a, float b, float c, float d) {
    asm volatile("red.global.add.v4.f32 [%0], {%1, %2, %3, %4};"
                 :: "l"(p), "f"(a), "f"(b), "f"(c), "f"(d) : "memory");
}
__device__ __forceinline__ void ffma2(ull& d, ull a, ull b) {
    asm("fma.rn.f32x2 %0, %1, %2, %0;" : "+l"(d) : "l"(a), "l"(b));
}
__device__ __forceinline__ ull pack2(float lo, float hi) {
    ull r; asm("mov.b64 %0, {%1, %2};" : "=l"(r) : "f"(lo), "f"(hi)); return r;
}
__device__ __forceinline__ void unpack2(float& lo, float& hi, ull v) {
    asm("mov.b64 {%0, %1}, %2;" : "=f"(lo), "=f"(hi) : "l"(v));
}
__device__ __forceinline__ unsigned bfpack(float lo, float hi) {
    unsigned r;
    asm("cvt.rn.bf16x2.f32 %0, %1, %2;" : "=r"(r) : "f"(hi), "f"(lo));
    return r;
}
__device__ __forceinline__ float bflo(unsigned u) { return __uint_as_float(u << 16); }
__device__ __forceinline__ float bfhi(unsigned u) { return __uint_as_float(u & 0xffff0000u); }

// ---------------- prep (indices + batch + degree count) ----------------
// g_wp and g_cnt are zero on entry (static init on first run; cleanup_kernel after).
__global__ __launch_bounds__(256) void prep_kernel(const void* ei_raw, const void* b_raw) {
    const int*       e32 = (const int*)ei_raw;
    const long long* e64 = (const long long*)ei_raw;
    bool is64 = true;
#pragma unroll
    for (int i = 0; i < 16; i++) is64 &= (e32[2 * i + 1] == 0);

    int idx = blockIdx.x * blockDim.x + threadIdx.x;
    if (idx < NET) {
        int s, d;
        if (idx < NE) {
            if (is64) { s = (int)e64[idx]; d = (int)e64[NE + idx]; }
            else      { s = e32[idx];      d = e32[NE + idx]; }
        } else { s = d = idx - NE; }
        g_src[idx] = s;
        g_dst[idx] = d;
        atomicAdd(&g_wp[d], 1);
    }
    if (idx < NN) {
        int b = is64 ? (int)((const long long*)b_raw)[idx] : ((const int*)b_raw)[idx];
        g_batch[idx] = b;
        atomicAdd(&g_cnt[b], 1.f);
    }
}

__global__ __launch_bounds__(1024) void scan_kernel() {
    __shared__ int part[1024];
    int t = threadIdx.x;
    const int CH = (NN + 1023) / 1024;
    int beg = t * CH, end = min(beg + CH, NN);
    int sum = 0;
    for (int i = beg; i < end; i++) sum += g_wp[i];
    part[t] = sum;
    __syncthreads();
    for (int off = 1; off < 1024; off <<= 1) {
        int v = (t >= off) ? part[t - off] : 0;
        __syncthreads();
        part[t] += v;
        __syncthreads();
    }
    int run = (t == 0) ? 0 : part[t - 1];
    for (int i = beg; i < end; i++) {
        int c = g_wp[i];
        g_rowptr[i] = run;
        g_wp[i] = run;
        run += c;
    }
    if (t == 1023) g_rowptr[NN] = run;
}

__global__ __launch_bounds__(256) void fill_kernel() {
    int e = blockIdx.x * blockDim.x + threadIdx.x;
    if (e >= NET) return;
    int pos = atomicAdd(&g_wp[g_dst[e]], 1);
    g_csrc[pos] = g_src[e];
}

// ---------------- f32x2 GEMM + fused attention-dot epilogue ----------------
// C[M,N] = A[M,K] @ B[K,N], stored bf16. BM=64, BN=128, BK=16, 128 threads,
// 8x8/thread, 4 CTAs/SM (barrier bubbles covered by sibling CTAs).
// Thread cols split {tx*4, 64+tx*4} (conflict-free B reads, per R13).
__global__ __launch_bounds__(128, 4) void gemm_kernel(
    const float* __restrict__ A, const float* __restrict__ B, __nv_bfloat16* __restrict__ C,
    int M, int N, int K,
    const float* __restrict__ avec, const float* __restrict__ dvec,
    float* __restrict__ as_out, float* __restrict__ ad_out, int multihead)
{
    __shared__ float As[16][68];    // transposed, 64 rows
    __shared__ float Bs[16][132];

    int tid = threadIdx.x;
    int lane = tid & 31;
    int rowBase = blockIdx.x * 64;
    int colBase = blockIdx.y * 128;
    int tx = tid & 15;
    int ty = tid >> 4;      // 0..7

    ull acc[4][8];   // [row-pair p][col j]: rows ty*8+2p{,+1}; j<4 -> tx*4+j, j>=4 -> 64+tx*4+j-4
#pragma unroll
    for (int p = 0; p < 4; p++)
#pragma unroll
        for (int j = 0; j < 8; j++) acc[p][j] = 0ull;

    for (int k0 = 0; k0 < K; k0 += 16) {
        // A chunk 64x16 -> 256 float4, 2/thread, stored transposed
#pragma unroll
        for (int i = 0; i < 2; i++) {
            int fid = tid + 128 * i;
            int r = fid >> 2, kq = (fid & 3) * 4;
            int row = rowBase + r;
            float4 v = make_float4(0.f, 0.f, 0.f, 0.f);
            if (row < M) v = *(const float4*)(A + (long long)row * K + k0 + kq);
            As[kq + 0][r] = v.x; As[kq + 1][r] = v.y;
            As[kq + 2][r] = v.z; As[kq + 3][r] = v.w;
        }
        // B chunk 16x128 -> 512 float4, 4/thread
#pragma unroll
        for (int i = 0; i < 4; i++) {
            int fid = tid + 128 * i;
            int rw = fid >> 5, cq = fid & 31;
            *(float4*)&Bs[rw][cq * 4] =
                *(const float4*)(B + (long long)(k0 + rw) * N + colBase + cq * 4);
        }
        __syncthreads();
#pragma unroll
        for (int kk = 0; kk < 16; kk++) {
            ulonglong2 a01 = *(const ulonglong2*)&As[kk][ty * 8];
            ulonglong2 a23 = *(const ulonglong2*)&As[kk][ty * 8 + 4];
            float4 b0 = *(const float4*)&Bs[kk][tx * 4];
            float4 b1 = *(const float4*)&Bs[kk][64 + tx * 4];
            ull rb[8];
            rb[0] = pack2(b0.x, b0.x); rb[1] = pack2(b0.y, b0.y);
            rb[2] = pack2(b0.z, b0.z); rb[3] = pack2(b0.w, b0.w);
            rb[4] = pack2(b1.x, b1.x); rb[5] = pack2(b1.y, b1.y);
            rb[6] = pack2(b1.z, b1.z); rb[7] = pack2(b1.w, b1.w);
            ull ra[4] = {a01.x, a01.y, a23.x, a23.y};
#pragma unroll
            for (int p = 0; p < 4; p++)
#pragma unroll
                for (int j = 0; j < 8; j++) ffma2(acc[p][j], ra[p], rb[j]);
        }
        __syncthreads();
    }

    // ---- epilogue: bf16 C store + fused attention dots (two col groups) ----
    float4 av0 = *(const float4*)(avec + colBase + tx * 4);
    float4 av1 = *(const float4*)(avec + colBase + 64 + tx * 4);
    float4 dv0 = *(const float4*)(dvec + colBase + tx * 4);
    float4 dv1 = *(const float4*)(dvec + colBase + 64 + tx * 4);
    float ds0[8], ds1[8], dd0[8], dd1[8];

#pragma unroll
    for (int p = 0; p < 4; p++) {
        float lo[8], hi[8];
#pragma unroll
        for (int j = 0; j < 8; j++) unpack2(lo[j], hi[j], acc[p][j]);
        int m0 = rowBase + ty * 8 + 2 * p;
        long long cb = (long long)m0 * N + colBase + tx * 4;
        if (m0 < M) {
            uint2 u0 = make_uint2(bfpack(lo[0], lo[1]), bfpack(lo[2], lo[3]));
            uint2 u1 = make_uint2(bfpack(lo[4], lo[5]), bfpack(lo[6], lo[7]));
            *(uint2*)(C + cb)      = u0;
            *(uint2*)(C + cb + 64) = u1;
        }
        if (m0 + 1 < M) {
            uint2 u0 = make_uint2(bfpack(hi[0], hi[1]), bfpack(hi[2], hi[3]));
            uint2 u1 = make_uint2(bfpack(hi[4], hi[5]), bfpack(hi[6], hi[7]));
            *(uint2*)(C + cb + N)      = u0;
            *(uint2*)(C + cb + N + 64) = u1;
        }
        ds0[2*p]   = lo[0]*av0.x + lo[1]*av0.y + lo[2]*av0.z + lo[3]*av0.w;
        ds1[2*p]   = lo[4]*av1.x + lo[5]*av1.y + lo[6]*av1.z + lo[7]*av1.w;
        dd0[2*p]   = lo[0]*dv0.x + lo[1]*dv0.y + lo[2]*dv0.z + lo[3]*dv0.w;
        dd1[2*p]   = lo[4]*dv1.x + lo[5]*dv1.y + lo[6]*dv1.z + lo[7]*dv1.w;
        ds0[2*p+1] = hi[0]*av0.x + hi[1]*av0.y + hi[2]*av0.z + hi[3]*av0.w;
        ds1[2*p+1] = hi[4]*av1.x + hi[5]*av1.y + hi[6]*av1.z + hi[7]*av1.w;
        dd0[2*p+1] = hi[0]*dv0.x + hi[1]*dv0.y + hi[2]*dv0.z + hi[3]*dv0.w;
        dd1[2*p+1] = hi[4]*dv1.x + hi[5]*dv1.y + hi[6]*dv1.z + hi[7]*dv1.w;
    }
    if (!multihead) {
#pragma unroll
        for (int rr = 0; rr < 8; rr++) { ds0[rr] += ds1[rr]; dd0[rr] += dd1[rr]; }
    }
#pragma unroll
    for (int rr = 0; rr < 8; rr++) {
#pragma unroll
        for (int off = 1; off <= 8; off <<= 1) {
            ds0[rr] += __shfl_xor_sync(0xffffffffu, ds0[rr], off);
            dd0[rr] += __shfl_xor_sync(0xffffffffu, dd0[rr], off);
        }
        if (multihead) {
#pragma unroll
            for (int off = 1; off <= 8; off <<= 1) {
                ds1[rr] += __shfl_xor_sync(0xffffffffu, ds1[rr], off);
                dd1[rr] += __shfl_xor_sync(0xffffffffu, dd1[rr], off);
            }
        }
    }
    int rowb = rowBase + ty * 8;
    if ((lane & 15) == 0) {
        if (multihead) {
            int h0 = colBase >> 6;   // block covers heads h0, h0+1
#pragma unroll
            for (int rr = 0; rr < 8; rr++) {
                int row = rowb + rr;
                if (row < M) {
                    as_out[row * 4 + h0]     = ds0[rr];
                    as_out[row * 4 + h0 + 1] = ds1[rr];
                    ad_out[row * 4 + h0]     = dd0[rr];
                    ad_out[row * 4 + h0 + 1] = dd1[rr];
                }
            }
        } else {
#pragma unroll
            for (int rr = 0; rr < 8; rr++) {
                int row = rowb + rr;
                if (row < M) {
                    as_out[row] = ds0[rr];
                    ad_out[row] = dd0[rr];
                }
            }
        }
    }
}

// ---------------- CSR aggregation (warp per dst node, R11/R13 proven form) ----------------
__global__ __launch_bounds__(256) void agg1_kernel(const float* __restrict__ b1) {
    int d = (blockIdx.x * blockDim.x + threadIdx.x) >> 5;
    int lane = threadIdx.x & 31;
    if (d >= NN) return;
    int h = lane >> 3;
    float ad = g_ad1[d * 4 + h];
    int beg = g_rowptr[d], end = g_rowptr[d + 1];
    float z = 0.f;
    float a[8] = {0.f, 0.f, 0.f, 0.f, 0.f, 0.f, 0.f, 0.f};
    for (int i = beg; i < end; i++) {
        int s = g_csrc[i];
        float w = __expf(lrelu(g_as1[s * 4 + h] + ad));
        z += w;
        uint4 v = *(const uint4*)(g_h1 + (size_t)s * D1 + lane * 8);
        a[0] += w * bflo(v.x); a[1] += w * bfhi(v.x);
        a[2] += w * bflo(v.y); a[3] += w * bfhi(v.y);
        a[4] += w * bflo(v.z); a[5] += w * bfhi(v.z);
        a[6] += w * bflo(v.w); a[7] += w * bfhi(v.w);
    }
    float inv = 1.f / z;
    const float4* bb = (const float4*)(b1 + lane * 8);
    float4 c0 = bb[0], c1 = bb[1];
    float4 o0, o1;
    o0.x = elu1(a[0] * inv + c0.x); o0.y = elu1(a[1] * inv + c0.y);
    o0.z = elu1(a[2] * inv + c0.z); o0.w = elu1(a[3] * inv + c0.w);
    o1.x = elu1(a[4] * inv + c1.x); o1.y = elu1(a[5] * inv + c1.y);
    o1.z = elu1(a[6] * inv + c1.z); o1.w = elu1(a[7] * inv + c1.w);
    float4* op = (float4*)(g_act1 + (size_t)d * D1 + lane * 8);
    op[0] = o0; op[1] = o1;
}

__global__ __launch_bounds__(256) void agg2_kernel(const float* __restrict__ b2) {
    int d = (blockIdx.x * blockDim.x + threadIdx.x) >> 5;
    int lane = threadIdx.x & 31;
    if (d >= NN) return;
    float ad = g_ad2[d];
    int beg = g_rowptr[d], end = g_rowptr[d + 1];
    float z = 0.f;
    float a[4] = {0.f, 0.f, 0.f, 0.f};
    for (int i = beg; i < end; i++) {
        int s = g_csrc[i];
        float w = __expf(lrelu(g_as2[s] + ad));
        z += w;
        uint2 v = *(const uint2*)(g_h2 + (size_t)s * EMB + lane * 4);
        a[0] += w * bflo(v.x); a[1] += w * bfhi(v.x);
        a[2] += w * bflo(v.y); a[3] += w * bfhi(v.y);
    }
    float inv = 1.f / z;
    float4 c = ((const float4*)b2)[lane];
    float o0 = elu1(a[0] * inv + c.x), o1 = elu1(a[1] * inv + c.y);
    float o2 = elu1(a[2] * inv + c.z), o3 = elu1(a[3] * inv + c.w);
    int b = g_batch[d];
    red4(&g_pool[b * EMB + lane * 4], o0, o1, o2, o3);
}

__global__ __launch_bounds__(256) void final_div_kernel(float* __restrict__ out) {
    int i = blockIdx.x * blockDim.x + threadIdx.x;
    if (i >= NG * EMB) return;
    out[i] = g_pool[i] / fmaxf(g_cnt[i >> 7], 1.f);
}

// re-zero accumulator state for the next (graph-replayed) run
__global__ __launch_bounds__(256) void cleanup_kernel() {
    int i = blockIdx.x * blockDim.x + threadIdx.x;
    if (i < NN)       g_wp[i]   = 0;
    if (i < NG * EMB) g_pool[i] = 0.f;
    if (i < NG)       g_cnt[i]  = 0.f;
}

// ---------------- launcher ----------------
extern "C" void kernel_launch(void* const* d_in, const int* in_sizes, int n_in,
                              void* d_out, int out_size)
{
    const float* x      = (const float*)d_in[0];
    const void*  ei     = d_in[1];
    const void*  batch  = d_in[3];
    const float* W1     = (const float*)d_in[4];
    const float* a_src1 = (const float*)d_in[5];
    const float* a_dst1 = (const float*)d_in[6];
    const float* b1     = (const float*)d_in[7];
    const float* W2     = (const float*)d_in[8];
    const float* a_src2 = (const float*)d_in[9];
    const float* a_dst2 = (const float*)d_in[10];
    const float* b2     = (const float*)d_in[11];
    float*       out    = (float*)d_out;

    __nv_bfloat16 *p_h1, *p_h2;
    float *p_act1, *p_as1, *p_ad1, *p_as2, *p_ad2;
    cudaGetSymbolAddress((void**)&p_h1,   g_h1);
    cudaGetSymbolAddress((void**)&p_act1, g_act1);
    cudaGetSymbolAddress((void**)&p_h2,   g_h2);
    cudaGetSymbolAddress((void**)&p_as1,  g_as1);
    cudaGetSymbolAddress((void**)&p_ad1,  g_ad1);
    cudaGetSymbolAddress((void**)&p_as2,  g_as2);
    cudaGetSymbolAddress((void**)&p_ad2,  g_ad2);

    static cudaStream_t s_side = nullptr;
    static cudaEvent_t  ev_fork = nullptr, ev_join = nullptr;
    if (!s_side) {
        cudaStreamCreateWithFlags(&s_side, cudaStreamNonBlocking);
        cudaEventCreateWithFlags(&ev_fork, cudaEventDisableTiming);
        cudaEventCreateWithFlags(&ev_join, cudaEventDisableTiming);
    }

    // fork: 3-kernel CSR build concurrent with GEMM1; gemm1 4th-submitted (profiled)
    cudaEventRecord(ev_fork, 0);
    cudaStreamWaitEvent(s_side, ev_fork, 0);
    prep_kernel<<<(NET + 255) / 256, 256, 0, s_side>>>(ei, batch);   // 1
    scan_kernel<<<1, 1024, 0, s_side>>>();                           // 2
    fill_kernel<<<(NET + 255) / 256, 256, 0, s_side>>>();            // 3
    cudaEventRecord(ev_join, s_side);

    gemm_kernel<<<dim3((NN + 63) / 64, D1 / 128), 128>>>(            // 4  <- profiled
        x, W1, p_h1, NN, D1, IND, a_src1, a_dst1, p_as1, p_ad1, 1);

    cudaStreamWaitEvent(0, ev_join, 0);
    agg1_kernel<<<(NN + 7) / 8, 256>>>(b1);                          // 5

    gemm_kernel<<<dim3((NN + 63) / 64, EMB / 128), 128>>>(           // 6
        p_act1, W2, p_h2, NN, EMB, D1, a_src2, a_dst2, p_as2, p_ad2, 0);
    agg2_kernel<<<(NN + 7) / 8, 256>>>(b2);                          // 7
    final_div_kernel<<<(NG * EMB + 255) / 256, 256>>>(out);          // 8
    cleanup_kernel<<<(NN + 255) / 256, 256>>>();                     // 9
}